// round 3
// baseline (speedup 1.0000x reference)
#include <cuda_runtime.h>

#define U_CNT 100000
#define I_CNT 50000
#define N_CNT 150000
#define DIM   64
#define NNZ_CNT 3200000
#define B_CNT 4096
#define NBW   ((N_CNT + 31) / 32)   // bitmap words

// ---- scratch (__device__ globals; allocation-free rule) ----
__device__ __align__(16) float g_cur1[N_CNT * DIM];
__device__ __align__(16) float g_cur2[N_CNT * DIM];
__device__ __align__(16) float g_cur3[N_CNT * DIM];

__device__ unsigned g_s3_bits[NBW];   // sampled nodes (rows read from c3)
__device__ unsigned g_s2_bits[NBW];   // nodes whose c2 is actually read
__device__ unsigned g_cnt3;

// compacted layer-3 edge list (expected ~173k, worst case NNZ)
__device__ int   g_l3_r[NNZ_CNT];
__device__ int   g_l3_c[NNZ_CNT];
__device__ float g_l3_v[NNZ_CNT];

__device__ __forceinline__ void red_add_v4(float* addr, float4 v) {
    asm volatile("red.global.add.v4.f32 [%0], {%1, %2, %3, %4};"
                 :: "l"(addr), "f"(v.x), "f"(v.y), "f"(v.z), "f"(v.w)
                 : "memory");
}

__device__ __forceinline__ bool test_bit(const unsigned* bits, int n) {
    return (__ldg(bits + (n >> 5)) >> (n & 31)) & 1u;
}

// ---- 1. zero c1, c2, bitmaps, counter ----
__global__ void zero_main_kernel() {
    unsigned t = blockIdx.x * blockDim.x + threadIdx.x;
    const unsigned n4 = (unsigned)N_CNT * DIM / 4;
    if (t < n4) {
        float4 z = make_float4(0.f, 0.f, 0.f, 0.f);
        reinterpret_cast<float4*>(g_cur1)[t] = z;
        reinterpret_cast<float4*>(g_cur2)[t] = z;
    }
    if (t < NBW) { g_s3_bits[t] = 0u; g_s2_bits[t] = 0u; }
    if (t == 0) { g_cnt3 = 0u; }
}

// ---- 2. zero c3 at sampled rows only + build S3 (and seed S2) ----
__global__ void prep_sampled_kernel(const int* __restrict__ users,
                                    const int* __restrict__ items) {
    int b = blockIdx.x;
    int tid = threadIdx.x;           // 0..127
    int half = tid >> 6;
    int j = tid & 63;
    int row = half ? __ldg(items + b) : __ldg(users + b);
    int node = half ? (U_CNT + row) : row;
    g_cur3[(size_t)node * DIM + j] = 0.f;
    if (j == 0) {
        atomicOr(&g_s3_bits[node >> 5], 1u << (node & 31));
        atomicOr(&g_s2_bits[node >> 5], 1u << (node & 31));
    }
}

// ---- 3. FUSED layer-1 SPMM (full) + layer-3 edge compaction + S2 marking ----
// 16 threads per edge; NNZ*16 divisible by 256 so all lanes are always active
// (required for the ballot below).
__global__ void spmm_l1_fused_kernel(const int* __restrict__ rows,
                                     const int* __restrict__ cols,
                                     const float* __restrict__ vals,
                                     const float* __restrict__ ue,
                                     const float* __restrict__ ie,
                                     float* __restrict__ y) {
    unsigned t = blockIdx.x * blockDim.x + threadIdx.x;
    unsigned e = t >> 4;
    int chunk = t & 15;
    int c = __ldg(cols + e);
    int r = __ldg(rows + e);
    float v = __ldg(vals + e);

    const float4* src = (c < U_CNT)
        ? reinterpret_cast<const float4*>(ue) + (size_t)c * 16
        : reinterpret_cast<const float4*>(ie) + (size_t)(c - U_CNT) * 16;
    float4 xv = __ldg(src + chunk);
    float4 o = make_float4(xv.x * v, xv.y * v, xv.z * v, xv.w * v);
    red_add_v4(y + (size_t)r * DIM + chunk * 4, o);

    // layer-3 edge discovery: only the chunk==0 lane of each edge
    bool pred = (chunk == 0) && test_bit(g_s3_bits, r);
    if (pred) atomicOr(&g_s2_bits[c >> 5], 1u << (c & 31));
    unsigned mask = __ballot_sync(0xffffffffu, pred);
    if (pred) {
        int lane = threadIdx.x & 31;
        int leader = __ffs(mask) - 1;
        unsigned base = 0;
        if (lane == leader) base = atomicAdd(&g_cnt3, (unsigned)__popc(mask));
        base = __shfl_sync(mask, base, leader);
        unsigned pos = base + __popc(mask & ((1u << lane) - 1u));
        g_l3_r[pos] = r; g_l3_c[pos] = c; g_l3_v[pos] = v;
    }
}

// ---- 4. layer-2 SPMM with inline S2 row filter ----
__global__ void spmm_l2_filtered_kernel(const int* __restrict__ rows,
                                        const int* __restrict__ cols,
                                        const float* __restrict__ vals,
                                        const float* __restrict__ x,
                                        float* __restrict__ y) {
    unsigned t = blockIdx.x * blockDim.x + threadIdx.x;
    unsigned e = t >> 4;
    int chunk = t & 15;
    int r = __ldg(rows + e);
    if (!test_bit(g_s2_bits, r)) return;   // same word for all 16 lanes: broadcast
    int c = __ldg(cols + e);
    float v = __ldg(vals + e);
    float4 xv = __ldg(reinterpret_cast<const float4*>(x) + (size_t)c * 16 + chunk);
    float4 o = make_float4(xv.x * v, xv.y * v, xv.z * v, xv.w * v);
    red_add_v4(y + (size_t)r * DIM + chunk * 4, o);
}

// ---- 5. layer-3 SPMM over the compacted list (grid-stride) ----
__global__ void spmm_list_kernel(const int* __restrict__ lr,
                                 const int* __restrict__ lc,
                                 const float* __restrict__ lv,
                                 const unsigned* __restrict__ cnt_ptr,
                                 const float* __restrict__ x,
                                 float* __restrict__ y) {
    unsigned total = __ldg(cnt_ptr) * 16u;
    unsigned stride = gridDim.x * blockDim.x;
    for (unsigned i = blockIdx.x * blockDim.x + threadIdx.x; i < total; i += stride) {
        unsigned e = i >> 4;
        int chunk = i & 15;
        int c = __ldg(lc + e);
        int r = __ldg(lr + e);
        float v = __ldg(lv + e);
        float4 xv = __ldg(reinterpret_cast<const float4*>(x) + (size_t)c * 16 + chunk);
        float4 o = make_float4(xv.x * v, xv.y * v, xv.z * v, xv.w * v);
        red_add_v4(y + (size_t)r * DIM + chunk * 4, o);
    }
}

// ---- 6. epilogue ----
__global__ void finalize_kernel(const float* __restrict__ ue,
                                const float* __restrict__ ie,
                                const float* __restrict__ W,
                                const float* __restrict__ bias,
                                const int* __restrict__ users,
                                const int* __restrict__ items,
                                const float* __restrict__ u_his,
                                const float* __restrict__ i_his,
                                float* __restrict__ out) {
    __shared__ float sWt[DIM * DIM];
    __shared__ float s_on[2][DIM];

    int b = blockIdx.x;
    int tid = threadIdx.x;  // 0..127

    for (int idx = tid; idx < DIM * DIM; idx += 128) {
        int j = idx >> 6, k = idx & 63;
        sWt[k * DIM + j] = W[idx];
    }

    int half = tid >> 6;
    int j = tid & 63;
    int row = half ? __ldg(items + b) : __ldg(users + b);
    int node = half ? (U_CNT + row) : row;
    const float* base = half ? ie : ue;

    size_t gi = (size_t)row * DIM + j;
    size_t ni = (size_t)node * DIM + j;
    float on = 0.25f * (base[gi] + g_cur1[ni] + g_cur2[ni] + g_cur3[ni]);
    s_on[half][j] = on;
    __syncthreads();

    float acc = __ldg(bias + j);
    const float* onv = s_on[half];
    #pragma unroll
    for (int k = 0; k < DIM; k++)
        acc = fmaf(onv[k], sWt[k * DIM + j], acc);

    const float* his = half ? i_his : u_his;
    float tgt = his[gi] * 0.05f + on * 0.95f;

    size_t seg = (size_t)B_CNT * DIM;
    out[(size_t)(half * 2) * seg + (size_t)b * DIM + j] = acc;
    out[(size_t)(half * 2 + 1) * seg + (size_t)b * DIM + j] = tgt;
}

extern "C" void kernel_launch(void* const* d_in, const int* in_sizes, int n_in,
                              void* d_out, int out_size) {
    const float* ue    = (const float*)d_in[0];
    const float* ie    = (const float*)d_in[1];
    const float* W     = (const float*)d_in[2];
    const float* bias  = (const float*)d_in[3];
    const int*   rows  = (const int*)d_in[4];
    const int*   cols  = (const int*)d_in[5];
    const float* vals  = (const float*)d_in[6];
    const int*   users = (const int*)d_in[7];
    const int*   items = (const int*)d_in[8];
    const float* u_his = (const float*)d_in[9];
    const float* i_his = (const float*)d_in[10];
    float* out = (float*)d_out;

    float *c1, *c2, *c3;
    cudaGetSymbolAddress((void**)&c1, g_cur1);
    cudaGetSymbolAddress((void**)&c2, g_cur2);
    cudaGetSymbolAddress((void**)&c3, g_cur3);
    unsigned *cnt3;
    cudaGetSymbolAddress((void**)&cnt3, g_cnt3);
    int *l3r, *l3c; float *l3v;
    cudaGetSymbolAddress((void**)&l3r, g_l3_r);
    cudaGetSymbolAddress((void**)&l3c, g_l3_c);
    cudaGetSymbolAddress((void**)&l3v, g_l3_v);

    // 1. zero c1, c2, bitmaps, counter
    {
        unsigned n4 = (unsigned)N_CNT * DIM / 4;
        zero_main_kernel<<<(n4 + 255) / 256, 256>>>();
    }
    // 2. zero c3 at sampled rows + build S3/S2 seed
    prep_sampled_kernel<<<B_CNT, 128>>>(users, items);

    unsigned spmm_threads = (unsigned)NNZ_CNT * 16;      // 51.2M, /256 exact
    unsigned spmm_blocks = spmm_threads / 256;

    // 3. fused layer-1 SPMM + layer-3 compaction + S2 marking
    spmm_l1_fused_kernel<<<spmm_blocks, 256>>>(rows, cols, vals, ue, ie, c1);
    // 4. layer-2 SPMM, inline S2 filter
    spmm_l2_filtered_kernel<<<spmm_blocks, 256>>>(rows, cols, vals, c1, c2);
    // 5. layer-3 SPMM over compacted list
    spmm_list_kernel<<<8192, 256>>>(l3r, l3c, l3v, cnt3, c2, c3);

    // 6. epilogue
    finalize_kernel<<<B_CNT, 128>>>(ue, ie, W, bias, users, items, u_his, i_his, out);
}

// round 4
// speedup vs baseline: 1.2894x; 1.2894x over previous
#include <cuda_runtime.h>

#define U_CNT 100000
#define I_CNT 50000
#define N_CNT 150000
#define DIM   64
#define NNZ_CNT 3200000
#define B_CNT 4096
#define NBW   ((N_CNT + 31) / 32)   // bitmap words

// ---- scratch (__device__ globals; allocation-free rule) ----
__device__ __align__(16) float g_cur1[N_CNT * DIM];
__device__ __align__(16) float g_cur2[N_CNT * DIM];
__device__ __align__(16) float g_cur3[N_CNT * DIM];

__device__ unsigned g_s3_bits[NBW];   // sampled nodes (rows read from c3)
__device__ unsigned g_s2_bits[NBW];   // nodes whose c2 is actually read
__device__ unsigned g_cnt3;
__device__ unsigned g_cnt2;

// compacted edge lists
__device__ int   g_l3_r[NNZ_CNT];
__device__ int   g_l3_c[NNZ_CNT];
__device__ float g_l3_v[NNZ_CNT];
__device__ int   g_l2_r[NNZ_CNT];
__device__ int   g_l2_c[NNZ_CNT];
__device__ float g_l2_v[NNZ_CNT];

__device__ __forceinline__ void red_add_v4(float* addr, float4 v) {
    asm volatile("red.global.add.v4.f32 [%0], {%1, %2, %3, %4};"
                 :: "l"(addr), "f"(v.x), "f"(v.y), "f"(v.z), "f"(v.w)
                 : "memory");
}

__device__ __forceinline__ bool test_bit(const unsigned* bits, int n) {
    return (__ldg(bits + (n >> 5)) >> (n & 31)) & 1u;
}

// ---- 1. zero c1, c2, bitmaps, counters ----
__global__ void zero_main_kernel() {
    unsigned t = blockIdx.x * blockDim.x + threadIdx.x;
    const unsigned n4 = (unsigned)N_CNT * DIM / 4;
    if (t < n4) {
        float4 z = make_float4(0.f, 0.f, 0.f, 0.f);
        reinterpret_cast<float4*>(g_cur1)[t] = z;
        reinterpret_cast<float4*>(g_cur2)[t] = z;
    }
    if (t < NBW) { g_s3_bits[t] = 0u; g_s2_bits[t] = 0u; }
    if (t == 0) { g_cnt3 = 0u; g_cnt2 = 0u; }
}

// ---- 2. zero c3 at sampled rows only + build S3 (and seed S2) ----
__global__ void prep_sampled_kernel(const int* __restrict__ users,
                                    const int* __restrict__ items) {
    int b = blockIdx.x;
    int tid = threadIdx.x;           // 0..127
    int half = tid >> 6;
    int j = tid & 63;
    int row = half ? __ldg(items + b) : __ldg(users + b);
    int node = half ? (U_CNT + row) : row;
    g_cur3[(size_t)node * DIM + j] = 0.f;
    if (j == 0) {
        atomicOr(&g_s3_bits[node >> 5], 1u << (node & 31));
        atomicOr(&g_s2_bits[node >> 5], 1u << (node & 31));
    }
}

// ---- block-aggregated compaction: one global atomic per block ----
// pass3: rows in S3 -> l3 list + mark S2 with cols
__global__ void passB_kernel(const int* __restrict__ rows,
                             const int* __restrict__ cols,
                             const float* __restrict__ vals) {
    __shared__ int   sr[256];
    __shared__ int   sc[256];
    __shared__ float sv[256];
    __shared__ unsigned s_cnt, s_base;
    int tid = threadIdx.x;
    unsigned e = blockIdx.x * 256u + tid;
    if (tid == 0) s_cnt = 0u;
    __syncthreads();

    int r = __ldg(rows + e);
    if (test_bit(g_s3_bits, r)) {
        int c = __ldg(cols + e);
        float v = __ldg(vals + e);
        atomicOr(&g_s2_bits[c >> 5], 1u << (c & 31));
        unsigned p = atomicAdd(&s_cnt, 1u);
        sr[p] = r; sc[p] = c; sv[p] = v;
    }
    __syncthreads();
    if (tid == 0 && s_cnt) s_base = atomicAdd(&g_cnt3, s_cnt);
    __syncthreads();
    unsigned n = s_cnt;
    if ((unsigned)tid < n) {
        unsigned o = s_base + tid;
        g_l3_r[o] = sr[tid]; g_l3_c[o] = sc[tid]; g_l3_v[o] = sv[tid];
    }
}

// pass2: rows in S2 -> l2 list
__global__ void passC_kernel(const int* __restrict__ rows,
                             const int* __restrict__ cols,
                             const float* __restrict__ vals) {
    __shared__ int   sr[256];
    __shared__ int   sc[256];
    __shared__ float sv[256];
    __shared__ unsigned s_cnt, s_base;
    int tid = threadIdx.x;
    unsigned e = blockIdx.x * 256u + tid;
    if (tid == 0) s_cnt = 0u;
    __syncthreads();

    int r = __ldg(rows + e);
    if (test_bit(g_s2_bits, r)) {
        int c = __ldg(cols + e);
        float v = __ldg(vals + e);
        unsigned p = atomicAdd(&s_cnt, 1u);
        sr[p] = r; sc[p] = c; sv[p] = v;
    }
    __syncthreads();
    if (tid == 0 && s_cnt) s_base = atomicAdd(&g_cnt2, s_cnt);
    __syncthreads();
    unsigned n = s_cnt;
    if ((unsigned)tid < n) {
        unsigned o = s_base + tid;
        g_l2_r[o] = sr[tid]; g_l2_c[o] = sc[tid]; g_l2_v[o] = sv[tid];
    }
}

// ---- layer-1 SPMM: full edge set, x = concat(user_emb, item_emb) ----
__global__ void spmm_first_kernel(const int* __restrict__ rows,
                                  const int* __restrict__ cols,
                                  const float* __restrict__ vals,
                                  const float* __restrict__ ue,
                                  const float* __restrict__ ie,
                                  float* __restrict__ y) {
    unsigned t = blockIdx.x * blockDim.x + threadIdx.x;
    unsigned e = t >> 4;
    int chunk = t & 15;
    int c = __ldg(cols + e);
    int r = __ldg(rows + e);
    float v = __ldg(vals + e);
    const float4* src = (c < U_CNT)
        ? reinterpret_cast<const float4*>(ue) + (size_t)c * 16
        : reinterpret_cast<const float4*>(ie) + (size_t)(c - U_CNT) * 16;
    float4 xv = __ldg(src + chunk);
    float4 o = make_float4(xv.x * v, xv.y * v, xv.z * v, xv.w * v);
    red_add_v4(y + (size_t)r * DIM + chunk * 4, o);
}

// ---- filtered SPMM over a compacted list (grid-stride, count device-side) ----
__global__ void spmm_list_kernel(const int* __restrict__ lr,
                                 const int* __restrict__ lc,
                                 const float* __restrict__ lv,
                                 const unsigned* __restrict__ cnt_ptr,
                                 const float* __restrict__ x,
                                 float* __restrict__ y) {
    unsigned total = __ldg(cnt_ptr) * 16u;
    unsigned stride = gridDim.x * blockDim.x;
    for (unsigned i = blockIdx.x * blockDim.x + threadIdx.x; i < total; i += stride) {
        unsigned e = i >> 4;
        int chunk = i & 15;
        int c = __ldg(lc + e);
        int r = __ldg(lr + e);
        float v = __ldg(lv + e);
        float4 xv = __ldg(reinterpret_cast<const float4*>(x) + (size_t)c * 16 + chunk);
        float4 o = make_float4(xv.x * v, xv.y * v, xv.z * v, xv.w * v);
        red_add_v4(y + (size_t)r * DIM + chunk * 4, o);
    }
}

// ---- epilogue ----
__global__ void finalize_kernel(const float* __restrict__ ue,
                                const float* __restrict__ ie,
                                const float* __restrict__ W,
                                const float* __restrict__ bias,
                                const int* __restrict__ users,
                                const int* __restrict__ items,
                                const float* __restrict__ u_his,
                                const float* __restrict__ i_his,
                                float* __restrict__ out) {
    __shared__ float sWt[DIM * DIM];
    __shared__ float s_on[2][DIM];

    int b = blockIdx.x;
    int tid = threadIdx.x;  // 0..127

    for (int idx = tid; idx < DIM * DIM; idx += 128) {
        int j = idx >> 6, k = idx & 63;
        sWt[k * DIM + j] = W[idx];
    }

    int half = tid >> 6;
    int j = tid & 63;
    int row = half ? __ldg(items + b) : __ldg(users + b);
    int node = half ? (U_CNT + row) : row;
    const float* base = half ? ie : ue;

    size_t gi = (size_t)row * DIM + j;
    size_t ni = (size_t)node * DIM + j;
    float on = 0.25f * (base[gi] + g_cur1[ni] + g_cur2[ni] + g_cur3[ni]);
    s_on[half][j] = on;
    __syncthreads();

    float acc = __ldg(bias + j);
    const float* onv = s_on[half];
    #pragma unroll
    for (int k = 0; k < DIM; k++)
        acc = fmaf(onv[k], sWt[k * DIM + j], acc);

    const float* his = half ? i_his : u_his;
    float tgt = his[gi] * 0.05f + on * 0.95f;

    size_t seg = (size_t)B_CNT * DIM;
    out[(size_t)(half * 2) * seg + (size_t)b * DIM + j] = acc;
    out[(size_t)(half * 2 + 1) * seg + (size_t)b * DIM + j] = tgt;
}

extern "C" void kernel_launch(void* const* d_in, const int* in_sizes, int n_in,
                              void* d_out, int out_size) {
    const float* ue    = (const float*)d_in[0];
    const float* ie    = (const float*)d_in[1];
    const float* W     = (const float*)d_in[2];
    const float* bias  = (const float*)d_in[3];
    const int*   rows  = (const int*)d_in[4];
    const int*   cols  = (const int*)d_in[5];
    const float* vals  = (const float*)d_in[6];
    const int*   users = (const int*)d_in[7];
    const int*   items = (const int*)d_in[8];
    const float* u_his = (const float*)d_in[9];
    const float* i_his = (const float*)d_in[10];
    float* out = (float*)d_out;

    float *c1, *c2, *c3;
    cudaGetSymbolAddress((void**)&c1, g_cur1);
    cudaGetSymbolAddress((void**)&c2, g_cur2);
    cudaGetSymbolAddress((void**)&c3, g_cur3);
    unsigned *cnt3, *cnt2;
    cudaGetSymbolAddress((void**)&cnt3, g_cnt3);
    cudaGetSymbolAddress((void**)&cnt2, g_cnt2);
    int *l3r, *l3c, *l2r, *l2c;
    float *l3v, *l2v;
    cudaGetSymbolAddress((void**)&l3r, g_l3_r);
    cudaGetSymbolAddress((void**)&l3c, g_l3_c);
    cudaGetSymbolAddress((void**)&l3v, g_l3_v);
    cudaGetSymbolAddress((void**)&l2r, g_l2_r);
    cudaGetSymbolAddress((void**)&l2c, g_l2_c);
    cudaGetSymbolAddress((void**)&l2v, g_l2_v);

    // 1. zero c1, c2, bitmaps, counters
    {
        unsigned n4 = (unsigned)N_CNT * DIM / 4;
        zero_main_kernel<<<(n4 + 255) / 256, 256>>>();
    }
    // 2. zero c3 at sampled rows + build S3/S2 seed
    prep_sampled_kernel<<<B_CNT, 128>>>(users, items);
    // 3. compact layer-3 edges (block-aggregated), mark S2
    passB_kernel<<<NNZ_CNT / 256, 256>>>(rows, cols, vals);
    // 4. compact layer-2 edges (block-aggregated)
    passC_kernel<<<NNZ_CNT / 256, 256>>>(rows, cols, vals);

    // 5. layer 1 (full)
    {
        unsigned spmm_threads = (unsigned)NNZ_CNT * 16;  // 51.2M, /256 exact
        spmm_first_kernel<<<spmm_threads / 256, 256>>>(rows, cols, vals, ue, ie, c1);
    }
    // 6. layer 2 (compacted list)
    spmm_list_kernel<<<16384, 256>>>(l2r, l2c, l2v, cnt2, c1, c2);
    // 7. layer 3 (compacted list)
    spmm_list_kernel<<<8192, 256>>>(l3r, l3c, l3v, cnt3, c2, c3);

    // 8. epilogue
    finalize_kernel<<<B_CNT, 128>>>(ue, ie, W, bias, users, items, u_his, i_his, out);
}

// round 5
// speedup vs baseline: 1.3553x; 1.0511x over previous
#include <cuda_runtime.h>

#define U_CNT 100000
#define I_CNT 50000
#define N_CNT 150000
#define DIM   64
#define NNZ_CNT 3200000
#define B_CNT 4096
#define NBW   ((N_CNT + 31) / 32)   // bitmap words

// ---- scratch (__device__ globals; allocation-free rule) ----
__device__ __align__(16) float g_cur1[N_CNT * DIM];
__device__ __align__(16) float g_cur2[N_CNT * DIM];
__device__ __align__(16) float g_cur3[N_CNT * DIM];

__device__ unsigned g_s3_bits[NBW];   // sampled nodes (rows read from c3)
__device__ unsigned g_s2_bits[NBW];   // nodes whose c2 is actually read
__device__ unsigned g_cnt3;
__device__ unsigned g_cnt2;

// compacted edge lists
__device__ int   g_l3_r[NNZ_CNT];
__device__ int   g_l3_c[NNZ_CNT];
__device__ float g_l3_v[NNZ_CNT];
__device__ int   g_l2_r[NNZ_CNT];
__device__ int   g_l2_c[NNZ_CNT];
__device__ float g_l2_v[NNZ_CNT];

__device__ __forceinline__ void red_add_v4(float* addr, float4 v) {
    asm volatile("red.global.add.v4.f32 [%0], {%1, %2, %3, %4};"
                 :: "l"(addr), "f"(v.x), "f"(v.y), "f"(v.z), "f"(v.w)
                 : "memory");
}

__device__ __forceinline__ bool test_bit(const unsigned* bits, int n) {
    return (__ldg(bits + (n >> 5)) >> (n & 31)) & 1u;
}

// ---- 1. zero c1, c2, bitmaps, counters ----
__global__ void zero_main_kernel() {
    unsigned t = blockIdx.x * blockDim.x + threadIdx.x;
    const unsigned n4 = (unsigned)N_CNT * DIM / 4;
    if (t < n4) {
        float4 z = make_float4(0.f, 0.f, 0.f, 0.f);
        reinterpret_cast<float4*>(g_cur1)[t] = z;
        reinterpret_cast<float4*>(g_cur2)[t] = z;
    }
    if (t < NBW) { g_s3_bits[t] = 0u; g_s2_bits[t] = 0u; }
    if (t == 0) { g_cnt3 = 0u; g_cnt2 = 0u; }
}

// ---- 2. zero c3 at sampled rows only + build S3 (and seed S2) ----
__global__ void prep_sampled_kernel(const int* __restrict__ users,
                                    const int* __restrict__ items) {
    int b = blockIdx.x;
    int tid = threadIdx.x;           // 0..127
    int half = tid >> 6;
    int j = tid & 63;
    int row = half ? __ldg(items + b) : __ldg(users + b);
    int node = half ? (U_CNT + row) : row;
    g_cur3[(size_t)node * DIM + j] = 0.f;
    if (j == 0) {
        atomicOr(&g_s3_bits[node >> 5], 1u << (node & 31));
        atomicOr(&g_s2_bits[node >> 5], 1u << (node & 31));
    }
}

// ---- block-aggregated compaction: one global atomic per block ----
// pass3: rows in S3 -> l3 list + mark S2 with cols
__global__ void passB_kernel(const int* __restrict__ rows,
                             const int* __restrict__ cols,
                             const float* __restrict__ vals) {
    __shared__ int   sr[256];
    __shared__ int   sc[256];
    __shared__ float sv[256];
    __shared__ unsigned s_cnt, s_base;
    int tid = threadIdx.x;
    unsigned e = blockIdx.x * 256u + tid;
    if (tid == 0) s_cnt = 0u;
    __syncthreads();

    int r = __ldg(rows + e);
    if (test_bit(g_s3_bits, r)) {
        int c = __ldg(cols + e);
        float v = __ldg(vals + e);
        atomicOr(&g_s2_bits[c >> 5], 1u << (c & 31));
        unsigned p = atomicAdd(&s_cnt, 1u);
        sr[p] = r; sc[p] = c; sv[p] = v;
    }
    __syncthreads();
    if (tid == 0 && s_cnt) s_base = atomicAdd(&g_cnt3, s_cnt);
    __syncthreads();
    unsigned n = s_cnt;
    if ((unsigned)tid < n) {
        unsigned o = s_base + tid;
        g_l3_r[o] = sr[tid]; g_l3_c[o] = sc[tid]; g_l3_v[o] = sv[tid];
    }
}

// pass2: rows in S2 -> l2 list
__global__ void passC_kernel(const int* __restrict__ rows,
                             const int* __restrict__ cols,
                             const float* __restrict__ vals) {
    __shared__ int   sr[256];
    __shared__ int   sc[256];
    __shared__ float sv[256];
    __shared__ unsigned s_cnt, s_base;
    int tid = threadIdx.x;
    unsigned e = blockIdx.x * 256u + tid;
    if (tid == 0) s_cnt = 0u;
    __syncthreads();

    int r = __ldg(rows + e);
    if (test_bit(g_s2_bits, r)) {
        int c = __ldg(cols + e);
        float v = __ldg(vals + e);
        unsigned p = atomicAdd(&s_cnt, 1u);
        sr[p] = r; sc[p] = c; sv[p] = v;
    }
    __syncthreads();
    if (tid == 0 && s_cnt) s_base = atomicAdd(&g_cnt2, s_cnt);
    __syncthreads();
    unsigned n = s_cnt;
    if ((unsigned)tid < n) {
        unsigned o = s_base + tid;
        g_l2_r[o] = sr[tid]; g_l2_c[o] = sc[tid]; g_l2_v[o] = sv[tid];
    }
}

// ---- layer-1 SPMM: full edge set, 4 threads/edge, 4 chunks/thread ----
// step k: lanes of an edge read/write base + k*64B + lane4*16B (coalesced 64B)
__global__ void spmm_first_kernel(const int* __restrict__ rows,
                                  const int* __restrict__ cols,
                                  const float* __restrict__ vals,
                                  const float* __restrict__ ue,
                                  const float* __restrict__ ie,
                                  float* __restrict__ y) {
    unsigned t = blockIdx.x * blockDim.x + threadIdx.x;
    unsigned e = t >> 2;
    int lane4 = t & 3;
    int c = __ldg(cols + e);
    int r = __ldg(rows + e);
    float v = __ldg(vals + e);
    const float4* src = (c < U_CNT)
        ? reinterpret_cast<const float4*>(ue) + (size_t)c * 16
        : reinterpret_cast<const float4*>(ie) + (size_t)(c - U_CNT) * 16;
    float4 xv[4];
    #pragma unroll
    for (int k = 0; k < 4; k++)
        xv[k] = __ldg(src + k * 4 + lane4);
    float* dst = y + (size_t)r * DIM + lane4 * 4;
    #pragma unroll
    for (int k = 0; k < 4; k++) {
        float4 o = make_float4(xv[k].x * v, xv[k].y * v, xv[k].z * v, xv[k].w * v);
        red_add_v4(dst + k * 16, o);
    }
}

// ---- filtered SPMM over a compacted list (grid-stride, 4 threads/edge) ----
__global__ void spmm_list_kernel(const int* __restrict__ lr,
                                 const int* __restrict__ lc,
                                 const float* __restrict__ lv,
                                 const unsigned* __restrict__ cnt_ptr,
                                 const float* __restrict__ x,
                                 float* __restrict__ y) {
    unsigned total = __ldg(cnt_ptr) * 4u;
    unsigned stride = gridDim.x * blockDim.x;
    for (unsigned i = blockIdx.x * blockDim.x + threadIdx.x; i < total; i += stride) {
        unsigned e = i >> 2;
        int lane4 = i & 3;
        int c = __ldg(lc + e);
        int r = __ldg(lr + e);
        float v = __ldg(lv + e);
        const float4* src = reinterpret_cast<const float4*>(x) + (size_t)c * 16;
        float4 xv[4];
        #pragma unroll
        for (int k = 0; k < 4; k++)
            xv[k] = __ldg(src + k * 4 + lane4);
        float* dst = y + (size_t)r * DIM + lane4 * 4;
        #pragma unroll
        for (int k = 0; k < 4; k++) {
            float4 o = make_float4(xv[k].x * v, xv[k].y * v, xv[k].z * v, xv[k].w * v);
            red_add_v4(dst + k * 16, o);
        }
    }
}

// ---- epilogue ----
__global__ void finalize_kernel(const float* __restrict__ ue,
                                const float* __restrict__ ie,
                                const float* __restrict__ W,
                                const float* __restrict__ bias,
                                const int* __restrict__ users,
                                const int* __restrict__ items,
                                const float* __restrict__ u_his,
                                const float* __restrict__ i_his,
                                float* __restrict__ out) {
    __shared__ float sWt[DIM * DIM];
    __shared__ float s_on[2][DIM];

    int b = blockIdx.x;
    int tid = threadIdx.x;  // 0..127

    for (int idx = tid; idx < DIM * DIM; idx += 128) {
        int j = idx >> 6, k = idx & 63;
        sWt[k * DIM + j] = W[idx];
    }

    int half = tid >> 6;
    int j = tid & 63;
    int row = half ? __ldg(items + b) : __ldg(users + b);
    int node = half ? (U_CNT + row) : row;
    const float* base = half ? ie : ue;

    size_t gi = (size_t)row * DIM + j;
    size_t ni = (size_t)node * DIM + j;
    float on = 0.25f * (base[gi] + g_cur1[ni] + g_cur2[ni] + g_cur3[ni]);
    s_on[half][j] = on;
    __syncthreads();

    float acc = __ldg(bias + j);
    const float* onv = s_on[half];
    #pragma unroll
    for (int k = 0; k < DIM; k++)
        acc = fmaf(onv[k], sWt[k * DIM + j], acc);

    const float* his = half ? i_his : u_his;
    float tgt = his[gi] * 0.05f + on * 0.95f;

    size_t seg = (size_t)B_CNT * DIM;
    out[(size_t)(half * 2) * seg + (size_t)b * DIM + j] = acc;
    out[(size_t)(half * 2 + 1) * seg + (size_t)b * DIM + j] = tgt;
}

extern "C" void kernel_launch(void* const* d_in, const int* in_sizes, int n_in,
                              void* d_out, int out_size) {
    const float* ue    = (const float*)d_in[0];
    const float* ie    = (const float*)d_in[1];
    const float* W     = (const float*)d_in[2];
    const float* bias  = (const float*)d_in[3];
    const int*   rows  = (const int*)d_in[4];
    const int*   cols  = (const int*)d_in[5];
    const float* vals  = (const float*)d_in[6];
    const int*   users = (const int*)d_in[7];
    const int*   items = (const int*)d_in[8];
    const float* u_his = (const float*)d_in[9];
    const float* i_his = (const float*)d_in[10];
    float* out = (float*)d_out;

    float *c1, *c2, *c3;
    cudaGetSymbolAddress((void**)&c1, g_cur1);
    cudaGetSymbolAddress((void**)&c2, g_cur2);
    cudaGetSymbolAddress((void**)&c3, g_cur3);
    unsigned *cnt3, *cnt2;
    cudaGetSymbolAddress((void**)&cnt3, g_cnt3);
    cudaGetSymbolAddress((void**)&cnt2, g_cnt2);
    int *l3r, *l3c, *l2r, *l2c;
    float *l3v, *l2v;
    cudaGetSymbolAddress((void**)&l3r, g_l3_r);
    cudaGetSymbolAddress((void**)&l3c, g_l3_c);
    cudaGetSymbolAddress((void**)&l3v, g_l3_v);
    cudaGetSymbolAddress((void**)&l2r, g_l2_r);
    cudaGetSymbolAddress((void**)&l2c, g_l2_c);
    cudaGetSymbolAddress((void**)&l2v, g_l2_v);

    // 1. zero c1, c2, bitmaps, counters
    {
        unsigned n4 = (unsigned)N_CNT * DIM / 4;
        zero_main_kernel<<<(n4 + 255) / 256, 256>>>();
    }
    // 2. zero c3 at sampled rows + build S3/S2 seed
    prep_sampled_kernel<<<B_CNT, 128>>>(users, items);
    // 3. compact layer-3 edges (block-aggregated), mark S2
    passB_kernel<<<NNZ_CNT / 256, 256>>>(rows, cols, vals);
    // 4. compact layer-2 edges (block-aggregated)
    passC_kernel<<<NNZ_CNT / 256, 256>>>(rows, cols, vals);

    // 5. layer 1 (full): 4 threads per edge
    spmm_first_kernel<<<(unsigned)NNZ_CNT * 4 / 256, 256>>>(rows, cols, vals, ue, ie, c1);
    // 6. layer 2 (compacted list)
    spmm_list_kernel<<<16384, 256>>>(l2r, l2c, l2v, cnt2, c1, c2);
    // 7. layer 3 (compacted list)
    spmm_list_kernel<<<4096, 256>>>(l3r, l3c, l3v, cnt3, c2, c3);

    // 8. epilogue
    finalize_kernel<<<B_CNT, 128>>>(ue, ie, W, bias, users, items, u_his, i_his, out);
}

// round 6
// speedup vs baseline: 2.1226x; 1.5661x over previous
#include <cuda_runtime.h>
#include <cuda_fp16.h>

#define U_CNT 100000
#define I_CNT 50000
#define N_CNT 150000
#define DIM   64
#define NNZ_CNT 3200000
#define B_CNT 4096
#define NBW   ((N_CNT + 31) / 32)   // bitmap words

// ---- scratch (__device__ globals; allocation-free rule) ----
__device__ __align__(16) __half g_egoh[N_CNT * DIM];   // fp16 copy of concat(ue, ie)
__device__ __align__(16) __half g_cur1h[N_CNT * DIM];
__device__ __align__(16) __half g_cur2h[N_CNT * DIM];
__device__ __align__(16) __half g_cur3h[N_CNT * DIM];

__device__ unsigned g_s3_bits[NBW];
__device__ unsigned g_s2_bits[NBW];
__device__ unsigned g_cnt3;
__device__ unsigned g_cnt2;

// compacted edge lists
__device__ int   g_l3_r[NNZ_CNT];
__device__ int   g_l3_c[NNZ_CNT];
__device__ float g_l3_v[NNZ_CNT];
__device__ int   g_l2_r[NNZ_CNT];
__device__ int   g_l2_c[NNZ_CNT];
__device__ float g_l2_v[NNZ_CNT];

__device__ __forceinline__ void red_add_h8(__half* addr, uint4 u) {
    asm volatile("red.global.add.noftz.v4.f16x2 [%0], {%1, %2, %3, %4};"
                 :: "l"(addr), "r"(u.x), "r"(u.y), "r"(u.z), "r"(u.w)
                 : "memory");
}

__device__ __forceinline__ bool test_bit(const unsigned* bits, int n) {
    return (__ldg(bits + (n >> 5)) >> (n & 31)) & 1u;
}

// multiply 8 packed halves by scalar v in fp32, repack
__device__ __forceinline__ uint4 mul_h8(uint4 u, float v) {
    uint4 o;
    unsigned* ui = &u.x;
    unsigned* oi = &o.x;
    #pragma unroll
    for (int i = 0; i < 4; i++) {
        __half2 h = *reinterpret_cast<__half2*>(&ui[i]);
        float2 f = __half22float2(h);
        f.x *= v; f.y *= v;
        __half2 r = __floats2half2_rn(f.x, f.y);
        oi[i] = *reinterpret_cast<unsigned*>(&r);
    }
    return o;
}

// ---- 1. zero c1h/c2h + convert ego to fp16 + zero bitmaps/counters ----
__global__ void zero_convert_kernel(const float* __restrict__ ue,
                                    const float* __restrict__ ie) {
    unsigned t = blockIdx.x * blockDim.x + threadIdx.x;
    const unsigned n16 = (unsigned)N_CNT * DIM / 8;  // 1.2M uint4 (8 halves each)
    if (t < n16) {
        uint4 z = make_uint4(0u, 0u, 0u, 0u);
        reinterpret_cast<uint4*>(g_cur1h)[t] = z;
        reinterpret_cast<uint4*>(g_cur2h)[t] = z;
        // convert 8 floats -> 8 halves
        const unsigned UF4 = (unsigned)U_CNT * DIM / 4;  // 1.6M float4 in ue
        unsigned f0 = 2u * t, f1 = 2u * t + 1u;
        float4 a = (f0 < UF4) ? __ldg(reinterpret_cast<const float4*>(ue) + f0)
                              : __ldg(reinterpret_cast<const float4*>(ie) + (f0 - UF4));
        float4 b = (f1 < UF4) ? __ldg(reinterpret_cast<const float4*>(ue) + f1)
                              : __ldg(reinterpret_cast<const float4*>(ie) + (f1 - UF4));
        uint4 o;
        __half2 h;
        h = __floats2half2_rn(a.x, a.y); o.x = *reinterpret_cast<unsigned*>(&h);
        h = __floats2half2_rn(a.z, a.w); o.y = *reinterpret_cast<unsigned*>(&h);
        h = __floats2half2_rn(b.x, b.y); o.z = *reinterpret_cast<unsigned*>(&h);
        h = __floats2half2_rn(b.z, b.w); o.w = *reinterpret_cast<unsigned*>(&h);
        reinterpret_cast<uint4*>(g_egoh)[t] = o;
    }
    if (t < NBW) { g_s3_bits[t] = 0u; g_s2_bits[t] = 0u; }
    if (t == 0) { g_cnt3 = 0u; g_cnt2 = 0u; }
}

// ---- 2. zero c3h at sampled rows + build S3 (seed S2) ----
__global__ void prep_sampled_kernel(const int* __restrict__ users,
                                    const int* __restrict__ items) {
    int b = blockIdx.x;
    int tid = threadIdx.x;           // 0..127
    int half_ = tid >> 6;
    int j = tid & 63;
    int row = half_ ? __ldg(items + b) : __ldg(users + b);
    int node = half_ ? (U_CNT + row) : row;
    g_cur3h[(size_t)node * DIM + j] = __float2half_rn(0.f);
    if (j == 0) {
        atomicOr(&g_s3_bits[node >> 5], 1u << (node & 31));
        atomicOr(&g_s2_bits[node >> 5], 1u << (node & 31));
    }
}

// ---- compaction passes: 4 edges/thread, block-aggregated global append ----
__global__ void passB_kernel(const int* __restrict__ rows,
                             const int* __restrict__ cols,
                             const float* __restrict__ vals) {
    __shared__ int   sr[1024];
    __shared__ int   sc[1024];
    __shared__ float sv[1024];
    __shared__ unsigned s_cnt, s_base;
    int tid = threadIdx.x;
    unsigned q = blockIdx.x * 256u + tid;     // quad index
    if (tid == 0) s_cnt = 0u;
    __syncthreads();

    int4   r4 = __ldg(reinterpret_cast<const int4*>(rows) + q);
    int4   c4 = __ldg(reinterpret_cast<const int4*>(cols) + q);
    float4 v4 = __ldg(reinterpret_cast<const float4*>(vals) + q);
    const int*   rr = &r4.x;
    const int*   cc = &c4.x;
    const float* vv = &v4.x;
    #pragma unroll
    for (int k = 0; k < 4; k++) {
        int r = rr[k];
        if (test_bit(g_s3_bits, r)) {
            int c = cc[k];
            atomicOr(&g_s2_bits[c >> 5], 1u << (c & 31));
            unsigned p = atomicAdd(&s_cnt, 1u);
            sr[p] = r; sc[p] = c; sv[p] = vv[k];
        }
    }
    __syncthreads();
    if (tid == 0 && s_cnt) s_base = atomicAdd(&g_cnt3, s_cnt);
    __syncthreads();
    unsigned n = s_cnt;
    for (unsigned i = tid; i < n; i += 256u) {
        unsigned o = s_base + i;
        g_l3_r[o] = sr[i]; g_l3_c[o] = sc[i]; g_l3_v[o] = sv[i];
    }
}

__global__ void passC_kernel(const int* __restrict__ rows,
                             const int* __restrict__ cols,
                             const float* __restrict__ vals) {
    __shared__ int   sr[1024];
    __shared__ int   sc[1024];
    __shared__ float sv[1024];
    __shared__ unsigned s_cnt, s_base;
    int tid = threadIdx.x;
    unsigned q = blockIdx.x * 256u + tid;
    if (tid == 0) s_cnt = 0u;
    __syncthreads();

    int4   r4 = __ldg(reinterpret_cast<const int4*>(rows) + q);
    int4   c4 = __ldg(reinterpret_cast<const int4*>(cols) + q);
    float4 v4 = __ldg(reinterpret_cast<const float4*>(vals) + q);
    const int*   rr = &r4.x;
    const int*   cc = &c4.x;
    const float* vv = &v4.x;
    #pragma unroll
    for (int k = 0; k < 4; k++) {
        int r = rr[k];
        if (test_bit(g_s2_bits, r)) {
            unsigned p = atomicAdd(&s_cnt, 1u);
            sr[p] = r; sc[p] = cc[k]; sv[p] = vv[k];
        }
    }
    __syncthreads();
    if (tid == 0 && s_cnt) s_base = atomicAdd(&g_cnt2, s_cnt);
    __syncthreads();
    unsigned n = s_cnt;
    for (unsigned i = tid; i < n; i += 256u) {
        unsigned o = s_base + i;
        g_l2_r[o] = sr[i]; g_l2_c[o] = sc[i]; g_l2_v[o] = sv[i];
    }
}

// ---- layer-1 SPMM: full edges, fp16 gather/RED, 4 threads/edge ----
// row = 8 uint4 chunks of 8 halves; thread lane4 handles chunks lane4 and lane4+4
__global__ void spmm_first_kernel(const int* __restrict__ rows,
                                  const int* __restrict__ cols,
                                  const float* __restrict__ vals) {
    unsigned t = blockIdx.x * blockDim.x + threadIdx.x;
    unsigned e = t >> 2;
    int lane4 = t & 3;
    int c = __ldg(cols + e);
    int r = __ldg(rows + e);
    float v = __ldg(vals + e);
    const uint4* src = reinterpret_cast<const uint4*>(g_egoh) + (size_t)c * 8;
    uint4 a = __ldg(src + lane4);
    uint4 b = __ldg(src + 4 + lane4);
    uint4 oa = mul_h8(a, v);
    uint4 ob = mul_h8(b, v);
    __half* dst = g_cur1h + (size_t)r * DIM;
    red_add_h8(dst + lane4 * 8, oa);
    red_add_h8(dst + (4 + lane4) * 8, ob);
}

// ---- filtered SPMM over compacted list, fp16, 4 threads/edge ----
__global__ void spmm_list_kernel(const int* __restrict__ lr,
                                 const int* __restrict__ lc,
                                 const float* __restrict__ lv,
                                 const unsigned* __restrict__ cnt_ptr,
                                 const __half* __restrict__ x,
                                 __half* __restrict__ y) {
    unsigned total = __ldg(cnt_ptr) * 4u;
    unsigned stride = gridDim.x * blockDim.x;
    for (unsigned i = blockIdx.x * blockDim.x + threadIdx.x; i < total; i += stride) {
        unsigned e = i >> 2;
        int lane4 = i & 3;
        int c = __ldg(lc + e);
        int r = __ldg(lr + e);
        float v = __ldg(lv + e);
        const uint4* src = reinterpret_cast<const uint4*>(x) + (size_t)c * 8;
        uint4 a = __ldg(src + lane4);
        uint4 b = __ldg(src + 4 + lane4);
        uint4 oa = mul_h8(a, v);
        uint4 ob = mul_h8(b, v);
        __half* dst = y + (size_t)r * DIM;
        red_add_h8(dst + lane4 * 8, oa);
        red_add_h8(dst + (4 + lane4) * 8, ob);
    }
}

// ---- epilogue: ego stays fp32, layer sums read as fp16 ----
__global__ void finalize_kernel(const float* __restrict__ ue,
                                const float* __restrict__ ie,
                                const float* __restrict__ W,
                                const float* __restrict__ bias,
                                const int* __restrict__ users,
                                const int* __restrict__ items,
                                const float* __restrict__ u_his,
                                const float* __restrict__ i_his,
                                float* __restrict__ out) {
    __shared__ float sWt[DIM * DIM];
    __shared__ float s_on[2][DIM];

    int b = blockIdx.x;
    int tid = threadIdx.x;  // 0..127

    for (int idx = tid; idx < DIM * DIM; idx += 128) {
        int j = idx >> 6, k = idx & 63;
        sWt[k * DIM + j] = W[idx];
    }

    int half_ = tid >> 6;
    int j = tid & 63;
    int row = half_ ? __ldg(items + b) : __ldg(users + b);
    int node = half_ ? (U_CNT + row) : row;
    const float* base = half_ ? ie : ue;

    size_t gi = (size_t)row * DIM + j;
    size_t ni = (size_t)node * DIM + j;
    float on = 0.25f * (base[gi]
                        + __half2float(g_cur1h[ni])
                        + __half2float(g_cur2h[ni])
                        + __half2float(g_cur3h[ni]));
    s_on[half_][j] = on;
    __syncthreads();

    float acc = __ldg(bias + j);
    const float* onv = s_on[half_];
    #pragma unroll
    for (int k = 0; k < DIM; k++)
        acc = fmaf(onv[k], sWt[k * DIM + j], acc);

    const float* his = half_ ? i_his : u_his;
    float tgt = his[gi] * 0.05f + on * 0.95f;

    size_t seg = (size_t)B_CNT * DIM;
    out[(size_t)(half_ * 2) * seg + (size_t)b * DIM + j] = acc;
    out[(size_t)(half_ * 2 + 1) * seg + (size_t)b * DIM + j] = tgt;
}

extern "C" void kernel_launch(void* const* d_in, const int* in_sizes, int n_in,
                              void* d_out, int out_size) {
    const float* ue    = (const float*)d_in[0];
    const float* ie    = (const float*)d_in[1];
    const float* W     = (const float*)d_in[2];
    const float* bias  = (const float*)d_in[3];
    const int*   rows  = (const int*)d_in[4];
    const int*   cols  = (const int*)d_in[5];
    const float* vals  = (const float*)d_in[6];
    const int*   users = (const int*)d_in[7];
    const int*   items = (const int*)d_in[8];
    const float* u_his = (const float*)d_in[9];
    const float* i_his = (const float*)d_in[10];
    float* out = (float*)d_out;

    __half *c1h, *c2h, *c3h;
    cudaGetSymbolAddress((void**)&c1h, g_cur1h);
    cudaGetSymbolAddress((void**)&c2h, g_cur2h);
    cudaGetSymbolAddress((void**)&c3h, g_cur3h);
    unsigned *cnt3, *cnt2;
    cudaGetSymbolAddress((void**)&cnt3, g_cnt3);
    cudaGetSymbolAddress((void**)&cnt2, g_cnt2);
    int *l3r, *l3c, *l2r, *l2c;
    float *l3v, *l2v;
    cudaGetSymbolAddress((void**)&l3r, g_l3_r);
    cudaGetSymbolAddress((void**)&l3c, g_l3_c);
    cudaGetSymbolAddress((void**)&l3v, g_l3_v);
    cudaGetSymbolAddress((void**)&l2r, g_l2_r);
    cudaGetSymbolAddress((void**)&l2c, g_l2_c);
    cudaGetSymbolAddress((void**)&l2v, g_l2_v);

    // 1. zero c1h/c2h + fp16 ego + bitmaps/counters
    {
        unsigned n16 = (unsigned)N_CNT * DIM / 8;  // 1.2M
        zero_convert_kernel<<<(n16 + 255) / 256, 256>>>(ue, ie);
    }
    // 2. zero c3h at sampled rows + S3/S2 seed
    prep_sampled_kernel<<<B_CNT, 128>>>(users, items);
    // 3./4. compact layer-3 then layer-2 edge lists (4 edges/thread)
    passB_kernel<<<NNZ_CNT / 1024, 256>>>(rows, cols, vals);
    passC_kernel<<<NNZ_CNT / 1024, 256>>>(rows, cols, vals);

    // 5. layer 1 (full, fp16)
    spmm_first_kernel<<<(unsigned)NNZ_CNT * 4 / 256, 256>>>(rows, cols, vals);
    // 6. layer 2 (compacted list)
    spmm_list_kernel<<<16384, 256>>>(l2r, l2c, l2v, cnt2, c1h, c2h);
    // 7. layer 3 (compacted list)
    spmm_list_kernel<<<4096, 256>>>(l3r, l3c, l3v, cnt3, c2h, c3h);

    // 8. epilogue
    finalize_kernel<<<B_CNT, 128>>>(ue, ie, W, bias, users, items, u_his, i_his, out);
}